// round 8
// baseline (speedup 1.0000x reference)
#include <cuda_runtime.h>
#include <math.h>
#include <stdint.h>

// One thread per antithetic PAIR; the +Z / -Z legs live in the two lanes of
// packed f32x2 registers (Blackwell FFMA2). Z staged via double-buffered
// cp.async smem pipeline (CH steps per chunk).
//
// Arithmetic recipe frozen from round 3 (rel_err 8.6e-6): fma exactly where a
// single-use mul feeds an add/sub, plain rn ops elsewhere, no constant
// refolding. Packed lanes perform bitwise-identical rn ops; subs are encoded
// as fma(b, -1, a) (bitwise equal); antithetic flip is an exact sign-bit XOR.

#define FMUL(a,b) __fmul_rn((a),(b))
#define FADD(a,b) __fadd_rn((a),(b))
#define FSUB(a,b) __fsub_rn((a),(b))
#define FMA(a,b,c) __fmaf_rn((a),(b),(c))

#define THREADS 64
#define PAIRS   64          // pairs per block (1 per thread)
#define CH      10          // steps per staged chunk (250 % 10 == 0)

typedef unsigned long long u64;

__device__ __forceinline__ u64 pk(float lo, float hi) {
    u64 r; asm("mov.b64 %0, {%1, %2};" : "=l"(r) : "f"(lo), "f"(hi)); return r;
}
__device__ __forceinline__ void upk(u64 v, float& lo, float& hi) {
    asm("mov.b64 {%0, %1}, %2;" : "=f"(lo), "=f"(hi) : "l"(v));
}
__device__ __forceinline__ u64 fma2(u64 a, u64 b, u64 c) {
    u64 d; asm("fma.rn.f32x2 %0, %1, %2, %3;" : "=l"(d) : "l"(a), "l"(b), "l"(c)); return d;
}
__device__ __forceinline__ u64 mul2(u64 a, u64 b) {
    u64 d; asm("mul.rn.f32x2 %0, %1, %2;" : "=l"(d) : "l"(a), "l"(b)); return d;
}
__device__ __forceinline__ float negf(float a) {
    return __uint_as_float(__float_as_uint(a) ^ 0x80000000u);
}

__global__ void __launch_bounds__(THREADS, 8) cpl_mc_kernel(
    const float* __restrict__ x0,  const float* __restrict__ v0,
    const float* __restrict__ p10, const float* __restrict__ p20,
    const float* __restrict__ p30, const float* __restrict__ p40,
    const float* __restrict__ p50, const float* __restrict__ p60,
    const float* __restrict__ s_kappa,  const float* __restrict__ s_theta,
    const float* __restrict__ s_rho,    const float* __restrict__ s_sigma,
    const float* __restrict__ s_alpha0, const float* __restrict__ s_alpha1,
    const float* __restrict__ s_gamma,  const float* __restrict__ s_varphi,
    const float* __restrict__ s_strike, const float* __restrict__ s_delta,
    const float* __restrict__ s_notional, const float* __restrict__ s_dt,
    const float* __restrict__ Z,
    float* __restrict__ out, int NH, int STEPS)
{
    __shared__ float zbuf[2][CH][2][PAIRS];

    const int tid   = threadIdx.x;
    const int ibase = blockIdx.x * PAIRS;
    const int pair  = tid;
    const int i     = ibase + pair;

    // ---- scalars ----
    const float kappa  = *s_kappa;
    const float theta  = *s_theta;
    const float rho    = *s_rho;
    const float sigma  = *s_sigma;
    const float alpha0 = *s_alpha0;
    const float alpha1 = *s_alpha1;
    const float g      = *s_gamma;
    const float varphi = *s_varphi;
    const float strike = *s_strike;
    const float delta  = *s_delta;
    const float notional = *s_notional;
    const float dt     = *s_dt;

    // ---- derived constants (plain rn ops, exact reference order) ----
    const float A  = FADD(__fdiv_rn(alpha0, g), __fdiv_rn(alpha1, FMUL(g, g)));
    const float Bc = __fdiv_rn(alpha1, g);
    const float sq1m = __fsqrt_rn(FSUB(1.0f, FMUL(rho, rho)));
    const float sqdt = __fsqrt_rn(dt);
    const float c5 = FADD(FMUL(alpha0, Bc), FMUL(alpha1, A));
    const float c6 = FMUL(alpha1, Bc);
    const float Aa0 = FMUL(A, alpha0);
    const float Aa1 = FMUL(A, alpha1);
    const float g2  = FMUL(2.0f, g);

    // ---- packed (broadcast) constants ----
    const u64 alpha0_2 = pk(alpha0, alpha0);
    const u64 alpha1_2 = pk(alpha1, alpha1);
    const u64 varphi_2 = pk(varphi, varphi);
    const u64 Aa0_2    = pk(Aa0, Aa0);
    const u64 Aa1_2    = pk(Aa1, Aa1);
    const u64 nc5_2    = pk(-c5, -c5);
    const u64 nc6_2    = pk(-c6, -c6);
    const u64 dt_2     = pk(dt, dt);
    const u64 ndt_2    = pk(-dt, -dt);
    const u64 g_2      = pk(g, g);
    const u64 ng_2     = pk(-g, -g);
    const u64 ng2_2    = pk(-g2, -g2);
    const u64 kappa_2  = pk(kappa, kappa);
    const u64 theta_2  = pk(theta, theta);
    const u64 sigma_2  = pk(sigma, sigma);
    const u64 two_2    = pk(2.0f, 2.0f);
    const u64 none_2   = pk(-1.0f, -1.0f);

    // ---- packed state: lane0 = +Z leg, lane1 = -Z leg ----
    u64 x2  = pk(x0[i],  x0[i]);
    u64 v2  = pk(v0[i],  v0[i]);
    u64 p1_2 = pk(p10[i], p10[i]);
    u64 p2_2 = pk(p20[i], p20[i]);
    u64 p3_2 = pk(p30[i], p30[i]);
    u64 p4_2 = pk(p40[i], p40[i]);
    u64 p5_2 = pk(p50[i], p50[i]);
    u64 p6_2 = pk(p60[i], p60[i]);
    u64 ir2 = pk(0.0f, 0.0f);

    const size_t stride = (size_t)2 * (size_t)NH;
    const int nch = (STEPS + CH - 1) / CH;

    auto load_chunk = [&](int c, int buf) {
        const int t0  = c * CH;
        const int len = min(CH, STEPS - t0);
        const int slots = len * (2 * PAIRS / 4);            // 16B slots
        const float* gbase = Z + (size_t)t0 * stride + ibase;
        #pragma unroll
        for (int r = 0; r < (CH * (2 * PAIRS / 4) + THREADS - 1) / THREADS; ++r) {
            const int s = tid + r * THREADS;
            if (s < slots) {
                const int k    = s >> 5;              // step within chunk
                const int half = (s >> 4) & 1;        // 0: zv row, 1: zp row
                const int q    = (s & 15) << 2;       // float offset in row
                const float* gp = gbase + (size_t)k * stride + (size_t)half * NH + q;
                const uint32_t sm = (uint32_t)__cvta_generic_to_shared(&zbuf[buf][k][half][q]);
                asm volatile("cp.async.cg.shared.global [%0], [%1], 16;\n"
                             :: "r"(sm), "l"(gp));
            }
        }
    };

    load_chunk(0, 0);
    asm volatile("cp.async.commit_group;\n");

    for (int c = 0; c < nch; ++c) {
        const int cur = c & 1;
        if (c + 1 < nch) {
            load_chunk(c + 1, cur ^ 1);
            asm volatile("cp.async.commit_group;\n");
            asm volatile("cp.async.wait_group 1;\n");
        } else {
            asm volatile("cp.async.wait_group 0;\n");
        }
        __syncthreads();

        const int len = min(CH, STEPS - c * CH);

        #pragma unroll
        for (int k = 0; k < CH; ++k) {
            if (k >= len) break;
            const float zv = zbuf[cur][k][0][pair];
            const float zp = zbuf[cur][k][1][pair];

            // scalar dW for lane0; lane1 = exact negation
            const float dWv = FMUL(sqdt, zv);
            const float dWx = FMUL(sqdt, FMA(rho, zv, FMUL(sq1m, zp)));
            const u64 dWv2 = pk(dWv, negf(dWv));
            const u64 dWx2 = pk(dWx, negf(dWx));

            // sv per lane (no packed MUFU): identical scalar ops to round 6
            float vA, vB; upk(v2, vA, vB);
            const float svA = __fsqrt_rn(fmaxf(vA, 0.0f));
            const float svB = __fsqrt_rn(fmaxf(vB, 0.0f));
            const u64 sv2 = pk(svA, svB);

            // r = varphi + a0*x + a1*p1 + Aa0*(p2-p3) + Aa1*p4 - c5*p5 - c6*p6
            u64 r2 = fma2(alpha0_2, x2, varphi_2);
            r2 = fma2(alpha1_2, p1_2, r2);
            const u64 d23 = fma2(p3_2, none_2, p2_2);     // == p2 - p3 bitwise
            r2 = fma2(Aa0_2, d23, r2);
            r2 = fma2(Aa1_2, p4_2, r2);
            r2 = fma2(nc5_2, p5_2, r2);
            r2 = fma2(nc6_2, p6_2, r2);
            ir2 = fma2(r2, dt_2, ir2);

            // xn = x - (g*x)*dt + sv*dWx   [fma(gx,-dt,x) == fma(-gx,dt,x)]
            const u64 gx2 = mul2(g_2, x2);
            const u64 xn2 = fma2(sv2, dWx2, fma2(gx2, ndt_2, x2));
            // vn = v + (kappa*(theta-v))*dt + (sigma*sv)*dWv
            const u64 tmv = fma2(v2, none_2, theta_2);    // == theta - v bitwise
            const u64 kv2 = mul2(kappa_2, tmv);
            const u64 ss2 = mul2(sigma_2, sv2);
            const u64 vn2 = fma2(ss2, dWv2, fma2(kv2, dt_2, v2));
            // pXn = pX + (u - c*pX)*dt
            const u64 t1 = fma2(ng_2,  p1_2, x2);    const u64 p1n = fma2(t1, dt_2, p1_2);
            const u64 t2 = fma2(ng_2,  p2_2, v2);    const u64 p2n = fma2(t2, dt_2, p2_2);
            const u64 t3 = fma2(ng2_2, p3_2, v2);    const u64 p3n = fma2(t3, dt_2, p3_2);
            const u64 t4 = fma2(ng_2,  p4_2, p2_2);  const u64 p4n = fma2(t4, dt_2, p4_2);
            const u64 t5 = fma2(ng2_2, p5_2, p3_2);  const u64 p5n = fma2(t5, dt_2, p5_2);
            const u64 p5x2 = mul2(two_2, p5_2);
            const u64 t6 = fma2(ng2_2, p6_2, p5x2);  const u64 p6n = fma2(t6, dt_2, p6_2);
            x2 = xn2; v2 = vn2;
            p1_2 = p1n; p2_2 = p2n; p3_2 = p3n; p4_2 = p4n; p5_2 = p5n; p6_2 = p6n;
        }
        __syncthreads();   // protect buffer being refilled next iteration
    }

    // ---- bond loadings (path-independent, plain rn ops) ----
    const float tau = delta;
    const float e1 = expf(-FMUL(g, tau));
    const float e2 = expf(-FMUL(FMUL(2.0f, g), tau));
    const float Bx = FADD(-A, FMUL(e1, FADD(A, FMUL(Bc, tau))));
    const float B1 = FMUL(Bc, FSUB(e1, 1.0f));
    const float B2 = FMUL(A, Bx);
    const float B4 = FMUL(A, B1);
    const float I0 = __fdiv_rn(FSUB(1.0f, e2), FMUL(2.0f, g));
    const float I1 = __fdiv_rn(FSUB(1.0f, FMUL(e2, FADD(1.0f, FMUL(FMUL(2.0f, g), tau)))),
                               FMUL(4.0f, FMUL(g, g)));
    const float g3 = FMUL(FMUL(g, g), g);
    const float inv4g3 = __fdiv_rn(1.0f, FMUL(4.0f, g3));
    const float I2 = FSUB(inv4g3,
                          FMUL(e2, FADD(FADD(__fdiv_rn(FMUL(tau, tau), FMUL(2.0f, g)),
                                             __fdiv_rn(tau, FMUL(2.0f, FMUL(g, g)))),
                                        inv4g3)));
    const float B3 = FADD(FADD(FMUL(FMUL(alpha0, A), I0), FMUL(c5, I1)), FMUL(c6, I2));
    const float B5 = FADD(FMUL(c5, I0), FMUL(FMUL(2.0f, c6), I1));
    const float B6 = FMUL(c6, I0);

    const float Kt    = __fdiv_rn(1.0f, FADD(1.0f, FMUL(delta, strike)));
    const float scale = FMUL(notional, FADD(1.0f, FMUL(delta, strike)));
    const float nvt   = -FMUL(varphi, tau);

    float xA, xB, vA_, vB_, p1A, p1B, p2A, p2B, p3A, p3B, p4A, p4B, p5A, p5B, p6A, p6B, irA, irB;
    upk(x2, xA, xB);   upk(v2, vA_, vB_);
    upk(p1_2, p1A, p1B); upk(p2_2, p2A, p2B); upk(p3_2, p3A, p3B);
    upk(p4_2, p4A, p4B); upk(p5_2, p5A, p5B); upk(p6_2, p6A, p6B);
    upk(ir2, irA, irB);

    {
        float logP = FADD(nvt, FMUL(Bx, xA));
        logP = FADD(logP, FMUL(B1, p1A));
        logP = FADD(logP, FMUL(B2, p2A));
        logP = FADD(logP, FMUL(B3, p3A));
        logP = FADD(logP, FMUL(B4, p4A));
        logP = FADD(logP, FMUL(B5, p5A));
        logP = FADD(logP, FMUL(B6, p6A));
        const float pT = expf(logP);
        const float pay = FMUL(scale, fmaxf(FSUB(Kt, pT), 0.0f));
        out[i] = FMUL(pay, expf(-irA));
    }
    {
        float logP = FADD(nvt, FMUL(Bx, xB));
        logP = FADD(logP, FMUL(B1, p1B));
        logP = FADD(logP, FMUL(B2, p2B));
        logP = FADD(logP, FMUL(B3, p3B));
        logP = FADD(logP, FMUL(B4, p4B));
        logP = FADD(logP, FMUL(B5, p5B));
        logP = FADD(logP, FMUL(B6, p6B));
        const float pT = expf(logP);
        const float pay = FMUL(scale, fmaxf(FSUB(Kt, pT), 0.0f));
        out[NH + i] = FMUL(pay, expf(-irB));
    }
}

extern "C" void kernel_launch(void* const* d_in, const int* in_sizes, int n_in,
                              void* d_out, int out_size)
{
    const float* x0  = (const float*)d_in[0];
    const float* v0  = (const float*)d_in[1];
    const float* p10 = (const float*)d_in[2];
    const float* p20 = (const float*)d_in[3];
    const float* p30 = (const float*)d_in[4];
    const float* p40 = (const float*)d_in[5];
    const float* p50 = (const float*)d_in[6];
    const float* p60 = (const float*)d_in[7];
    const float* kappa   = (const float*)d_in[8];
    const float* theta   = (const float*)d_in[9];
    const float* rho     = (const float*)d_in[10];
    const float* sigma   = (const float*)d_in[11];
    const float* alpha0  = (const float*)d_in[12];
    const float* alpha1  = (const float*)d_in[13];
    const float* gamma_  = (const float*)d_in[14];
    const float* varphi  = (const float*)d_in[15];
    const float* strike  = (const float*)d_in[16];
    const float* delta   = (const float*)d_in[17];
    const float* notional= (const float*)d_in[18];
    const float* dt      = (const float*)d_in[19];
    const float* Z       = (const float*)d_in[20];

    const int NH    = in_sizes[0];
    const int STEPS = in_sizes[20] / (2 * NH);

    float* out = (float*)d_out;

    const int blocks = (NH + PAIRS - 1) / PAIRS;
    cpl_mc_kernel<<<blocks, THREADS>>>(
        x0, v0, p10, p20, p30, p40, p50, p60,
        kappa, theta, rho, sigma, alpha0, alpha1, gamma_, varphi,
        strike, delta, notional, dt, Z, out, NH, STEPS);
}

// round 9
// speedup vs baseline: 1.1621x; 1.1621x over previous
#include <cuda_runtime.h>
#include <math.h>
#include <stdint.h>

// One thread per PATH (2*NH threads). Even thread = +Z leg, odd thread = -Z
// leg of the same antithetic pair. Z staged through shared memory with a
// double-buffered cp.async pipeline (CH-step chunks).
//
// Antithetic flip folded into per-thread SIGNED constants (bitwise identical
// to negating z: IEEE rn negation commutes through mul/fma operands).
//
// In-loop arithmetic mirrors XLA:GPU's LLVM "contract" FMA formation
// (validated round 3, rel_err 8.639e-6): fma exactly where a single-use mul
// feeds an add/sub; inner muls stay muls; no constant pre-folding.

#define FMUL(a,b) __fmul_rn((a),(b))
#define FADD(a,b) __fadd_rn((a),(b))
#define FSUB(a,b) __fsub_rn((a),(b))
#define FMA(a,b,c) __fmaf_rn((a),(b),(c))

#define THREADS 128
#define PAIRS   64          // pairs per block
#define CH      10          // steps per staged chunk (250 % 10 == 0)

__global__ void __launch_bounds__(THREADS, 7) cpl_mc_kernel(
    const float* __restrict__ x0,  const float* __restrict__ v0,
    const float* __restrict__ p10, const float* __restrict__ p20,
    const float* __restrict__ p30, const float* __restrict__ p40,
    const float* __restrict__ p50, const float* __restrict__ p60,
    const float* __restrict__ s_kappa,  const float* __restrict__ s_theta,
    const float* __restrict__ s_rho,    const float* __restrict__ s_sigma,
    const float* __restrict__ s_alpha0, const float* __restrict__ s_alpha1,
    const float* __restrict__ s_gamma,  const float* __restrict__ s_varphi,
    const float* __restrict__ s_strike, const float* __restrict__ s_delta,
    const float* __restrict__ s_notional, const float* __restrict__ s_dt,
    const float* __restrict__ Z,
    float* __restrict__ out, int NH, int STEPS)
{
    __shared__ float zbuf[2][CH][2][PAIRS];

    const int tid   = threadIdx.x;
    const int ibase = blockIdx.x * PAIRS;          // first pair of this block
    const int pair  = tid >> 1;                     // local pair 0..63
    const int i     = ibase + pair;                 // global pair index
    const bool neg  = (tid & 1);                    // odd thread = -Z leg

    // ---- scalars ----
    const float kappa  = *s_kappa;
    const float theta  = *s_theta;
    const float rho    = *s_rho;
    const float sigma  = *s_sigma;
    const float alpha0 = *s_alpha0;
    const float alpha1 = *s_alpha1;
    const float g      = *s_gamma;
    const float varphi = *s_varphi;
    const float strike = *s_strike;
    const float delta  = *s_delta;
    const float notional = *s_notional;
    const float dt     = *s_dt;

    // ---- derived constants: plain rn ops, exact reference order ----
    const float A  = FADD(__fdiv_rn(alpha0, g), __fdiv_rn(alpha1, FMUL(g, g)));
    const float Bc = __fdiv_rn(alpha1, g);
    const float sq1m = __fsqrt_rn(FSUB(1.0f, FMUL(rho, rho)));
    const float sqdt = __fsqrt_rn(dt);
    const float c5 = FADD(FMUL(alpha0, Bc), FMUL(alpha1, A));
    const float c6 = FMUL(alpha1, Bc);
    const float Aa0 = FMUL(A, alpha0);
    const float Aa1 = FMUL(A, alpha1);
    const float g2  = FMUL(2.0f, g);

    // ---- per-thread signed constants (exact antithetic flip) ----
    const float rho_t  = neg ? -rho  : rho;    // for dWx inner fma
    const float s1m_t  = neg ? -sq1m : sq1m;   // for dWx inner mul
    const float sqdv_t = neg ? -sqdt : sqdt;   // for dWv

    // ---- state ----
    float x  = x0[i];
    float v  = v0[i];
    float p1 = p10[i];
    float p2 = p20[i];
    float p3 = p30[i];
    float p4 = p40[i];
    float p5 = p50[i];
    float p6 = p60[i];
    float ir = 0.0f;

    const size_t stride = (size_t)2 * (size_t)NH;
    const int nfull = STEPS / CH;          // full chunks through smem pipeline
    const int trem  = nfull * CH;          // first remainder step (none at 250)

    // one Euler step; zv/zp are the RAW (+Z) normals; signed constants flip.
    auto step = [&](float zv, float zp) {
        const float dWv = FMUL(sqdv_t, zv);
        const float dWx = FMUL(sqdt, FMA(rho_t, zv, FMUL(s1m_t, zp)));

        const float sv = __fsqrt_rn(fmaxf(v, 0.0f));
        float r = FMA(alpha0, x, varphi);
        r = FMA(alpha1, p1, r);
        r = FMA(Aa0, FSUB(p2, p3), r);
        r = FMA(Aa1, p4, r);
        r = FMA(-c5, p5, r);
        r = FMA(-c6, p6, r);
        ir = FMA(r, dt, ir);

        // xn = x - (g*x)*dt + sv*dWx
        const float gx = FMUL(g, x);
        const float xn = FMA(sv, dWx, FMA(-gx, dt, x));
        // vn = v + (kappa*(theta-v))*dt + (sigma*sv)*dWv
        const float kv = FMUL(kappa, FSUB(theta, v));
        const float ss = FMUL(sigma, sv);
        const float vn = FMA(ss, dWv, FMA(kv, dt, v));
        // pXn = pX + (u - c*pX)*dt
        const float t1 = FMA(-g,  p1, x);    const float p1n = FMA(t1, dt, p1);
        const float t2 = FMA(-g,  p2, v);    const float p2n = FMA(t2, dt, p2);
        const float t3 = FMA(-g2, p3, v);    const float p3n = FMA(t3, dt, p3);
        const float t4 = FMA(-g,  p4, p2);   const float p4n = FMA(t4, dt, p4);
        const float t5 = FMA(-g2, p5, p3);   const float p5n = FMA(t5, dt, p5);
        const float p5x2 = FMUL(2.0f, p5);
        const float t6 = FMA(-g2, p6, p5x2); const float p6n = FMA(t6, dt, p6);
        x = xn; v = vn;
        p1 = p1n; p2 = p2n; p3 = p3n; p4 = p4n; p5 = p5n; p6 = p6n;
    };

    // ---- chunk loader: CH full steps -> zbuf[buf] via cp.async ----
    auto load_chunk = [&](int c, int buf) {
        const float* gbase = Z + (size_t)(c * CH) * stride + ibase;
        #pragma unroll
        for (int r = 0; r < (CH * 32 + THREADS - 1) / THREADS; ++r) {
            const int s = tid + r * THREADS;
            if (s < CH * 32) {                        // 16B slots: CH*2*16
                const int k    = s >> 5;
                const int half = (s >> 4) & 1;
                const int q    = (s & 15) << 2;       // float offset
                const float* gp = gbase + (size_t)k * stride + (size_t)half * NH + q;
                const uint32_t sm = (uint32_t)__cvta_generic_to_shared(&zbuf[buf][k][half][q]);
                asm volatile("cp.async.cg.shared.global [%0], [%1], 16;\n"
                             :: "r"(sm), "l"(gp));
            }
        }
    };

    if (nfull > 0) {
        load_chunk(0, 0);
        asm volatile("cp.async.commit_group;\n");

        for (int c = 0; c < nfull; ++c) {
            const int cur = c & 1;
            if (c + 1 < nfull) {
                load_chunk(c + 1, cur ^ 1);
                asm volatile("cp.async.commit_group;\n");
                asm volatile("cp.async.wait_group 1;\n");
            } else {
                asm volatile("cp.async.wait_group 0;\n");
            }
            __syncthreads();

            #pragma unroll
            for (int k = 0; k < CH; ++k)
                step(zbuf[cur][k][0][pair], zbuf[cur][k][1][pair]);

            __syncthreads();   // protect buffer being refilled next iteration
        }
    }

    // remainder steps (STEPS % CH) straight from global — not taken at 250
    for (int t = trem; t < STEPS; ++t) {
        const float* zr = Z + (size_t)t * stride;
        step(__ldcs(zr + i), __ldcs(zr + NH + i));
    }

    // ---- bond loadings (path-independent, plain rn ops) ----
    const float tau = delta;
    const float e1 = expf(-FMUL(g, tau));
    const float e2 = expf(-FMUL(FMUL(2.0f, g), tau));
    const float Bx = FADD(-A, FMUL(e1, FADD(A, FMUL(Bc, tau))));
    const float B1 = FMUL(Bc, FSUB(e1, 1.0f));
    const float B2 = FMUL(A, Bx);
    const float B4 = FMUL(A, B1);
    const float I0 = __fdiv_rn(FSUB(1.0f, e2), FMUL(2.0f, g));
    const float I1 = __fdiv_rn(FSUB(1.0f, FMUL(e2, FADD(1.0f, FMUL(FMUL(2.0f, g), tau)))),
                               FMUL(4.0f, FMUL(g, g)));
    const float g3 = FMUL(FMUL(g, g), g);
    const float inv4g3 = __fdiv_rn(1.0f, FMUL(4.0f, g3));
    const float I2 = FSUB(inv4g3,
                          FMUL(e2, FADD(FADD(__fdiv_rn(FMUL(tau, tau), FMUL(2.0f, g)),
                                             __fdiv_rn(tau, FMUL(2.0f, FMUL(g, g)))),
                                        inv4g3)));
    const float B3 = FADD(FADD(FMUL(FMUL(alpha0, A), I0), FMUL(c5, I1)), FMUL(c6, I2));
    const float B5 = FADD(FMUL(c5, I0), FMUL(FMUL(2.0f, c6), I1));
    const float B6 = FMUL(c6, I0);

    const float Kt    = __fdiv_rn(1.0f, FADD(1.0f, FMUL(delta, strike)));
    const float scale = FMUL(notional, FADD(1.0f, FMUL(delta, strike)));
    const float nvt   = -FMUL(varphi, tau);

    float logP = FADD(nvt, FMUL(Bx, x));
    logP = FADD(logP, FMUL(B1, p1));
    logP = FADD(logP, FMUL(B2, p2));
    logP = FADD(logP, FMUL(B3, p3));
    logP = FADD(logP, FMUL(B4, p4));
    logP = FADD(logP, FMUL(B5, p5));
    logP = FADD(logP, FMUL(B6, p6));
    const float pT = expf(logP);
    const float pay = FMUL(scale, fmaxf(FSUB(Kt, pT), 0.0f));
    out[(neg ? NH : 0) + i] = FMUL(pay, expf(-ir));
}

extern "C" void kernel_launch(void* const* d_in, const int* in_sizes, int n_in,
                              void* d_out, int out_size)
{
    const float* x0  = (const float*)d_in[0];
    const float* v0  = (const float*)d_in[1];
    const float* p10 = (const float*)d_in[2];
    const float* p20 = (const float*)d_in[3];
    const float* p30 = (const float*)d_in[4];
    const float* p40 = (const float*)d_in[5];
    const float* p50 = (const float*)d_in[6];
    const float* p60 = (const float*)d_in[7];
    const float* kappa   = (const float*)d_in[8];
    const float* theta   = (const float*)d_in[9];
    const float* rho     = (const float*)d_in[10];
    const float* sigma   = (const float*)d_in[11];
    const float* alpha0  = (const float*)d_in[12];
    const float* alpha1  = (const float*)d_in[13];
    const float* gamma_  = (const float*)d_in[14];
    const float* varphi  = (const float*)d_in[15];
    const float* strike  = (const float*)d_in[16];
    const float* delta   = (const float*)d_in[17];
    const float* notional= (const float*)d_in[18];
    const float* dt      = (const float*)d_in[19];
    const float* Z       = (const float*)d_in[20];

    const int NH    = in_sizes[0];
    const int STEPS = in_sizes[20] / (2 * NH);

    float* out = (float*)d_out;

    const int total  = 2 * NH;
    const int blocks = (total + THREADS - 1) / THREADS;
    cpl_mc_kernel<<<blocks, THREADS>>>(
        x0, v0, p10, p20, p30, p40, p50, p60,
        kappa, theta, rho, sigma, alpha0, alpha1, gamma_, varphi,
        strike, delta, notional, dt, Z, out, NH, STEPS);
}

// round 10
// speedup vs baseline: 1.4995x; 1.2903x over previous
#include <cuda_runtime.h>
#include <math.h>
#include <stdint.h>

// One thread per PATH (2*NH threads). Even thread = +Z leg, odd thread = -Z
// leg of the same antithetic pair. Z staged through shared memory with a
// double-buffered cp.async pipeline (CH-step chunks).
//
// Antithetic flip folded into per-thread SIGNED constants (bitwise identical
// to negating z). In-loop arithmetic mirrors XLA:GPU's LLVM "contract" FMA
// formation (validated round 3). Only deliberate deviation: sqrt.approx for
// the per-step sqrt(max(v,0)) — error contribution ~3e-7 rel, budget 1e-3.

#define FMUL(a,b) __fmul_rn((a),(b))
#define FADD(a,b) __fadd_rn((a),(b))
#define FSUB(a,b) __fsub_rn((a),(b))
#define FMA(a,b,c) __fmaf_rn((a),(b),(c))

#define THREADS 128
#define PAIRS   64          // pairs per block
#define CH      25          // steps per staged chunk (250 % 25 == 0)

__device__ __forceinline__ float sqrt_approx(float a) {
    float r; asm("sqrt.approx.f32 %0, %1;" : "=f"(r) : "f"(a)); return r;
}

__global__ void __launch_bounds__(THREADS, 7) cpl_mc_kernel(
    const float* __restrict__ x0,  const float* __restrict__ v0,
    const float* __restrict__ p10, const float* __restrict__ p20,
    const float* __restrict__ p30, const float* __restrict__ p40,
    const float* __restrict__ p50, const float* __restrict__ p60,
    const float* __restrict__ s_kappa,  const float* __restrict__ s_theta,
    const float* __restrict__ s_rho,    const float* __restrict__ s_sigma,
    const float* __restrict__ s_alpha0, const float* __restrict__ s_alpha1,
    const float* __restrict__ s_gamma,  const float* __restrict__ s_varphi,
    const float* __restrict__ s_strike, const float* __restrict__ s_delta,
    const float* __restrict__ s_notional, const float* __restrict__ s_dt,
    const float* __restrict__ Z,
    float* __restrict__ out, int NH, int STEPS)
{
    __shared__ float zbuf[2][CH][2][PAIRS];

    const int tid   = threadIdx.x;
    const int ibase = blockIdx.x * PAIRS;          // first pair of this block
    const int pair  = tid >> 1;                     // local pair 0..63
    const int i     = ibase + pair;                 // global pair index
    const bool neg  = (tid & 1);                    // odd thread = -Z leg

    // ---- scalars ----
    const float kappa  = *s_kappa;
    const float theta  = *s_theta;
    const float rho    = *s_rho;
    const float sigma  = *s_sigma;
    const float alpha0 = *s_alpha0;
    const float alpha1 = *s_alpha1;
    const float g      = *s_gamma;
    const float varphi = *s_varphi;
    const float strike = *s_strike;
    const float delta  = *s_delta;
    const float notional = *s_notional;
    const float dt     = *s_dt;

    // ---- derived constants: plain rn ops, exact reference order ----
    const float A  = FADD(__fdiv_rn(alpha0, g), __fdiv_rn(alpha1, FMUL(g, g)));
    const float Bc = __fdiv_rn(alpha1, g);
    const float sq1m = __fsqrt_rn(FSUB(1.0f, FMUL(rho, rho)));
    const float sqdt = __fsqrt_rn(dt);
    const float c5 = FADD(FMUL(alpha0, Bc), FMUL(alpha1, A));
    const float c6 = FMUL(alpha1, Bc);
    const float Aa0 = FMUL(A, alpha0);
    const float Aa1 = FMUL(A, alpha1);
    const float g2  = FMUL(2.0f, g);

    // ---- per-thread signed constants (exact antithetic flip) ----
    const float rho_t  = neg ? -rho  : rho;    // for dWx inner fma
    const float s1m_t  = neg ? -sq1m : sq1m;   // for dWx inner mul
    const float sqdv_t = neg ? -sqdt : sqdt;   // for dWv

    // ---- state ----
    float x  = x0[i];
    float v  = v0[i];
    float p1 = p10[i];
    float p2 = p20[i];
    float p3 = p30[i];
    float p4 = p40[i];
    float p5 = p50[i];
    float p6 = p60[i];
    float ir = 0.0f;

    const size_t stride = (size_t)2 * (size_t)NH;
    const int nfull = STEPS / CH;          // full chunks through smem pipeline
    const int trem  = nfull * CH;          // first remainder step (none at 250)

    // one Euler step; zv/zp are the RAW (+Z) normals; signed constants flip.
    auto step = [&](float zv, float zp) {
        const float dWv = FMUL(sqdv_t, zv);
        const float dWx = FMUL(sqdt, FMA(rho_t, zv, FMUL(s1m_t, zp)));

        const float sv = sqrt_approx(fmaxf(v, 0.0f));
        float r = FMA(alpha0, x, varphi);
        r = FMA(alpha1, p1, r);
        r = FMA(Aa0, FSUB(p2, p3), r);
        r = FMA(Aa1, p4, r);
        r = FMA(-c5, p5, r);
        r = FMA(-c6, p6, r);
        ir = FMA(r, dt, ir);

        // xn = x - (g*x)*dt + sv*dWx
        const float gx = FMUL(g, x);
        const float xn = FMA(sv, dWx, FMA(-gx, dt, x));
        // vn = v + (kappa*(theta-v))*dt + (sigma*sv)*dWv
        const float kv = FMUL(kappa, FSUB(theta, v));
        const float ss = FMUL(sigma, sv);
        const float vn = FMA(ss, dWv, FMA(kv, dt, v));
        // pXn = pX + (u - c*pX)*dt
        const float t1 = FMA(-g,  p1, x);    const float p1n = FMA(t1, dt, p1);
        const float t2 = FMA(-g,  p2, v);    const float p2n = FMA(t2, dt, p2);
        const float t3 = FMA(-g2, p3, v);    const float p3n = FMA(t3, dt, p3);
        const float t4 = FMA(-g,  p4, p2);   const float p4n = FMA(t4, dt, p4);
        const float t5 = FMA(-g2, p5, p3);   const float p5n = FMA(t5, dt, p5);
        const float p5x2 = FMUL(2.0f, p5);
        const float t6 = FMA(-g2, p6, p5x2); const float p6n = FMA(t6, dt, p6);
        x = xn; v = vn;
        p1 = p1n; p2 = p2n; p3 = p3n; p4 = p4n; p5 = p5n; p6 = p6n;
    };

    // ---- chunk loader: CH full steps -> zbuf[buf] via cp.async ----
    auto load_chunk = [&](int c, int buf) {
        const float* gbase = Z + (size_t)(c * CH) * stride + ibase;
        #pragma unroll
        for (int r = 0; r < (CH * 32 + THREADS - 1) / THREADS; ++r) {
            const int s = tid + r * THREADS;
            if (s < CH * 32) {                        // 16B slots: CH*2*16
                const int k    = s >> 5;
                const int half = (s >> 4) & 1;
                const int q    = (s & 15) << 2;       // float offset
                const float* gp = gbase + (size_t)k * stride + (size_t)half * NH + q;
                const uint32_t sm = (uint32_t)__cvta_generic_to_shared(&zbuf[buf][k][half][q]);
                asm volatile("cp.async.cg.shared.global [%0], [%1], 16;\n"
                             :: "r"(sm), "l"(gp));
            }
        }
    };

    if (nfull > 0) {
        load_chunk(0, 0);
        asm volatile("cp.async.commit_group;\n");

        for (int c = 0; c < nfull; ++c) {
            const int cur = c & 1;
            if (c + 1 < nfull) {
                load_chunk(c + 1, cur ^ 1);
                asm volatile("cp.async.commit_group;\n");
                asm volatile("cp.async.wait_group 1;\n");
            } else {
                asm volatile("cp.async.wait_group 0;\n");
            }
            __syncthreads();

            #pragma unroll
            for (int k = 0; k < CH; ++k)
                step(zbuf[cur][k][0][pair], zbuf[cur][k][1][pair]);

            __syncthreads();   // protect buffer being refilled next iteration
        }
    }

    // remainder steps (STEPS % CH) straight from global — not taken at 250
    for (int t = trem; t < STEPS; ++t) {
        const float* zr = Z + (size_t)t * stride;
        step(__ldcs(zr + i), __ldcs(zr + NH + i));
    }

    // ---- bond loadings (path-independent, plain rn ops) ----
    const float tau = delta;
    const float e1 = expf(-FMUL(g, tau));
    const float e2 = expf(-FMUL(FMUL(2.0f, g), tau));
    const float Bx = FADD(-A, FMUL(e1, FADD(A, FMUL(Bc, tau))));
    const float B1 = FMUL(Bc, FSUB(e1, 1.0f));
    const float B2 = FMUL(A, Bx);
    const float B4 = FMUL(A, B1);
    const float I0 = __fdiv_rn(FSUB(1.0f, e2), FMUL(2.0f, g));
    const float I1 = __fdiv_rn(FSUB(1.0f, FMUL(e2, FADD(1.0f, FMUL(FMUL(2.0f, g), tau)))),
                               FMUL(4.0f, FMUL(g, g)));
    const float g3 = FMUL(FMUL(g, g), g);
    const float inv4g3 = __fdiv_rn(1.0f, FMUL(4.0f, g3));
    const float I2 = FSUB(inv4g3,
                          FMUL(e2, FADD(FADD(__fdiv_rn(FMUL(tau, tau), FMUL(2.0f, g)),
                                             __fdiv_rn(tau, FMUL(2.0f, FMUL(g, g)))),
                                        inv4g3)));
    const float B3 = FADD(FADD(FMUL(FMUL(alpha0, A), I0), FMUL(c5, I1)), FMUL(c6, I2));
    const float B5 = FADD(FMUL(c5, I0), FMUL(FMUL(2.0f, c6), I1));
    const float B6 = FMUL(c6, I0);

    const float Kt    = __fdiv_rn(1.0f, FADD(1.0f, FMUL(delta, strike)));
    const float scale = FMUL(notional, FADD(1.0f, FMUL(delta, strike)));
    const float nvt   = -FMUL(varphi, tau);

    float logP = FADD(nvt, FMUL(Bx, x));
    logP = FADD(logP, FMUL(B1, p1));
    logP = FADD(logP, FMUL(B2, p2));
    logP = FADD(logP, FMUL(B3, p3));
    logP = FADD(logP, FMUL(B4, p4));
    logP = FADD(logP, FMUL(B5, p5));
    logP = FADD(logP, FMUL(B6, p6));
    const float pT = expf(logP);
    const float pay = FMUL(scale, fmaxf(FSUB(Kt, pT), 0.0f));
    out[(neg ? NH : 0) + i] = FMUL(pay, expf(-ir));
}

extern "C" void kernel_launch(void* const* d_in, const int* in_sizes, int n_in,
                              void* d_out, int out_size)
{
    const float* x0  = (const float*)d_in[0];
    const float* v0  = (const float*)d_in[1];
    const float* p10 = (const float*)d_in[2];
    const float* p20 = (const float*)d_in[3];
    const float* p30 = (const float*)d_in[4];
    const float* p40 = (const float*)d_in[5];
    const float* p50 = (const float*)d_in[6];
    const float* p60 = (const float*)d_in[7];
    const float* kappa   = (const float*)d_in[8];
    const float* theta   = (const float*)d_in[9];
    const float* rho     = (const float*)d_in[10];
    const float* sigma   = (const float*)d_in[11];
    const float* alpha0  = (const float*)d_in[12];
    const float* alpha1  = (const float*)d_in[13];
    const float* gamma_  = (const float*)d_in[14];
    const float* varphi  = (const float*)d_in[15];
    const float* strike  = (const float*)d_in[16];
    const float* delta   = (const float*)d_in[17];
    const float* notional= (const float*)d_in[18];
    const float* dt      = (const float*)d_in[19];
    const float* Z       = (const float*)d_in[20];

    const int NH    = in_sizes[0];
    const int STEPS = in_sizes[20] / (2 * NH);

    float* out = (float*)d_out;

    const int total  = 2 * NH;
    const int blocks = (total + THREADS - 1) / THREADS;
    cpl_mc_kernel<<<blocks, THREADS>>>(
        x0, v0, p10, p20, p30, p40, p50, p60,
        kappa, theta, rho, sigma, alpha0, alpha1, gamma_, varphi,
        strike, delta, notional, dt, Z, out, NH, STEPS);
}